// round 2
// baseline (speedup 1.0000x reference)
#include <cuda_runtime.h>
#include <math.h>

#define BVOL  (128*128*128)     // one batch volume: 2,097,152
#define VOL   (2*BVOL)          // full I/S tensor:  4,194,304
#define PLANE (128*128)         // 16384
#define FVOL  (2*3*BVOL)        // F tensor: 12,582,912

// Scratch (allocation-free rule: __device__ globals)
__device__ float  g_tmpA[2*VOL];   // [0..VOL) = gt after pass, [VOL..2VOL) = pred
__device__ float  g_tmpB[2*VOL];
__device__ double g_acc[12];
// acc layout: 0 reg_sumsq | 1 gg0 2 pp0 3 gp0 | 4 gg1 5 pp1 6 gp1 | 7 tvgp0 8 tvsum0 | 9 tvgp1 10 tvsum1

__global__ void zero_acc_kernel() {
    if (threadIdx.x < 12) g_acc[threadIdx.x] = 0.0;
}

__device__ __forceinline__ float warpSum(float v) {
#pragma unroll
    for (int o = 16; o; o >>= 1) v += __shfl_down_sync(0xffffffffu, v, o);
    return v;
}

// ---------------------------------------------------------------------------
// Separable box pass along Z (stride PLANE) or Y (stride 128).
// 131072 threads: 32768 columns x 4 segments of 32. Each thread reads its
// 32(+4 halo) inputs once via a register sliding window, writes 32 outputs.
// Adjacent threads -> adjacent x -> fully coalesced.
// ---------------------------------------------------------------------------
template<int STRIDE, bool ZPASS>
__global__ void box_pass(const float* __restrict__ in, float* __restrict__ out) {
    int u   = blockIdx.x * blockDim.x + threadIdx.x;   // 0..131071
    int c   = u & 32767;                               // column id (x fastest)
    int s   = u >> 15;                                 // segment 0..3
    int n   = c >> 14;
    int rem = c & 16383;
    int a   = rem >> 7;                                // y (zpass) or z (ypass)
    int x   = rem & 127;
    long base = ZPASS ? ((long)n * BVOL + a * 128 + x)
                      : ((long)n * BVOL + a * PLANE + x);
    const float* p = in  + base;
    float*       q = out + base;
    int z0 = s * 32;

    float w0 = (z0 >= 2) ? p[(z0 - 2) * STRIDE] : 0.f;
    float w1 = (z0 >= 1) ? p[(z0 - 1) * STRIDE] : 0.f;
    float w2 = p[(z0 + 0) * STRIDE];
    float w3 = p[(z0 + 1) * STRIDE];
#pragma unroll
    for (int i = 0; i < 32; i++) {
        int zl = z0 + i + 2;
        float w4 = (zl < 128) ? p[zl * STRIDE] : 0.f;
        q[(z0 + i) * STRIDE] = 0.2f * (((w0 + w1) + (w2 + w3)) + w4);
        w0 = w1; w1 = w2; w2 = w3; w3 = w4;
    }
}

// ---------------------------------------------------------------------------
// Final X-pass (stride 1) fused with the LCC reduction.
// 256-thread blocks, two 128-long x-lines per block-iteration, grid-stride
// over all 32768 lines. Computes m_gt, m_pred from smem lines, then
// d = orig - m and accumulates sum(dg*dg), sum(dp*dp), sum(dg*dp).
// ---------------------------------------------------------------------------
__global__ void xpass_reduce(const float* __restrict__ tg, const float* __restrict__ tp,
                             const float* __restrict__ og, const float* __restrict__ op,
                             int accBase) {
    __shared__ float sg[2][136];
    __shared__ float sp[2][136];
    __shared__ float red[3][8];

    int t   = threadIdx.x;
    int sub = t >> 7;        // 0 or 1
    int xi  = t & 127;
    float agg = 0.f, app = 0.f, agp = 0.f;

    int step = gridDim.x * 2;
    for (int line = blockIdx.x * 2 + sub; line < 32768; line += step) {
        long base = (long)line * 128;
        sg[sub][xi + 2] = tg[base + xi];
        sp[sub][xi + 2] = tp[base + xi];
        if (xi < 2) {
            sg[sub][xi] = 0.f;       sp[sub][xi] = 0.f;
            sg[sub][130 + xi] = 0.f; sp[sub][130 + xi] = 0.f;
        }
        __syncthreads();
        float mg = 0.2f * (((sg[sub][xi] + sg[sub][xi+1]) + (sg[sub][xi+2] + sg[sub][xi+3])) + sg[sub][xi+4]);
        float mp = 0.2f * (((sp[sub][xi] + sp[sub][xi+1]) + (sp[sub][xi+2] + sp[sub][xi+3])) + sp[sub][xi+4]);
        float dg = og[base + xi] - mg;
        float dp = op[base + xi] - mp;
        agg += dg * dg;
        app += dp * dp;
        agp += dg * dp;
        __syncthreads();
    }

    agg = warpSum(agg); app = warpSum(app); agp = warpSum(agp);
    int lane = t & 31, wid = t >> 5;
    if (lane == 0) { red[0][wid] = agg; red[1][wid] = app; red[2][wid] = agp; }
    __syncthreads();
    if (wid == 0) {
        float a  = (lane < 8) ? red[0][lane] : 0.f;
        float b  = (lane < 8) ? red[1][lane] : 0.f;
        float cc = (lane < 8) ? red[2][lane] : 0.f;
        a = warpSum(a); b = warpSum(b); cc = warpSum(cc);
        if (lane == 0) {
            atomicAdd(&g_acc[accBase + 0], (double)a);
            atomicAdd(&g_acc[accBase + 1], (double)b);
            atomicAdd(&g_acc[accBase + 2], (double)cc);
        }
    }
}

// ---------------------------------------------------------------------------
// reg_field: sum((pred-gt)^2) over F tensors, float4 grid-stride.
// ---------------------------------------------------------------------------
__global__ void reg_reduce(const float4* __restrict__ a, const float4* __restrict__ b, int n4) {
    int tid = blockIdx.x * blockDim.x + threadIdx.x;
    int tot = gridDim.x * blockDim.x;
    float s = 0.f;
    for (int i = tid; i < n4; i += tot) {
        float4 x = a[i], y = b[i];
        float d0 = x.x - y.x, d1 = x.y - y.y, d2 = x.z - y.z, d3 = x.w - y.w;
        s += d0 * d0 + d1 * d1 + d2 * d2 + d3 * d3;
    }
    s = warpSum(s);
    __shared__ float red[8];
    int lane = threadIdx.x & 31, wid = threadIdx.x >> 5;
    if (lane == 0) red[wid] = s;
    __syncthreads();
    if (wid == 0) {
        float v = (lane < 8) ? red[lane] : 0.f;
        v = warpSum(v);
        if (lane == 0) atomicAdd(&g_acc[0], (double)v);
    }
}

// ---------------------------------------------------------------------------
// tversky: sum(g*p) and sum(g+p), float4 grid-stride.
// ---------------------------------------------------------------------------
__global__ void tversky_reduce(const float4* __restrict__ g, const float4* __restrict__ p,
                               int n4, int accBase) {
    int tid = blockIdx.x * blockDim.x + threadIdx.x;
    int tot = gridDim.x * blockDim.x;
    float sgp = 0.f, ssm = 0.f;
    for (int i = tid; i < n4; i += tot) {
        float4 a = g[i], b = p[i];
        sgp += a.x * b.x + a.y * b.y + a.z * b.z + a.w * b.w;
        ssm += (a.x + b.x) + (a.y + b.y) + (a.z + b.z) + (a.w + b.w);
    }
    sgp = warpSum(sgp); ssm = warpSum(ssm);
    __shared__ float red[2][8];
    int lane = threadIdx.x & 31, wid = threadIdx.x >> 5;
    if (lane == 0) { red[0][wid] = sgp; red[1][wid] = ssm; }
    __syncthreads();
    if (wid == 0) {
        float a = (lane < 8) ? red[0][lane] : 0.f;
        float b = (lane < 8) ? red[1][lane] : 0.f;
        a = warpSum(a); b = warpSum(b);
        if (lane == 0) {
            atomicAdd(&g_acc[accBase + 0], (double)a);
            atomicAdd(&g_acc[accBase + 1], (double)b);
        }
    }
}

__global__ void finalize_kernel(float* out) {
    double reg = sqrt(g_acc[0]) / (double)FVOL;

    double den0 = g_acc[1] * g_acc[2]; if (den0 < 1e-5) den0 = 1e-5;
    double lcc0 = -((g_acc[3] * g_acc[3]) / den0) / (double)VOL;
    double den1 = g_acc[4] * g_acc[5]; if (den1 < 1e-5) den1 = 1e-5;
    double lcc1 = -((g_acc[6] * g_acc[6]) / den1) / (double)VOL;

    double ds0 = g_acc[8];  if (ds0 < 1e-5) ds0 = 1e-5;
    double tv0 = -g_acc[7] / ds0;
    double ds1 = g_acc[10]; if (ds1 < 1e-5) ds1 = 1e-5;
    double tv1 = -g_acc[9] / ds1;

    out[0] = (float)(reg + 10.0 * (lcc0 + lcc1) + 10.0 * (tv0 + tv1));
}

extern "C" void kernel_launch(void* const* d_in, const int* in_sizes, int n_in,
                              void* d_out, int out_size) {
    const float* F0  = (const float*)d_in[0];
    const float* F0g = (const float*)d_in[1];
    const float* I0  = (const float*)d_in[2];
    const float* I0R = (const float*)d_in[3];
    const float* I1  = (const float*)d_in[4];
    const float* I1R = (const float*)d_in[5];
    const float* S0  = (const float*)d_in[6];
    const float* S0g = (const float*)d_in[7];
    const float* S1  = (const float*)d_in[8];
    const float* S1g = (const float*)d_in[9];
    float* out = (float*)d_out;

    float* tA = nullptr;
    float* tB = nullptr;
    cudaGetSymbolAddress((void**)&tA, g_tmpA);
    cudaGetSymbolAddress((void**)&tB, g_tmpB);

    zero_acc_kernel<<<1, 32>>>();

    // independent plain reductions
    reg_reduce<<<1024, 256>>>((const float4*)F0, (const float4*)F0g, FVOL / 4);
    tversky_reduce<<<512, 256>>>((const float4*)S0, (const float4*)S0g, VOL / 4, 7);
    tversky_reduce<<<512, 256>>>((const float4*)S1, (const float4*)S1g, VOL / 4, 9);

    // LCC pair 0: z-pass, y-pass, fused x-pass + reduction
    box_pass<PLANE, true ><<<512, 256>>>(I0,        tA);
    box_pass<PLANE, true ><<<512, 256>>>(I0R,       tA + VOL);
    box_pass<128,   false><<<512, 256>>>(tA,        tB);
    box_pass<128,   false><<<512, 256>>>(tA + VOL,  tB + VOL);
    xpass_reduce<<<1024, 256>>>(tB, tB + VOL, I0, I0R, 1);

    // LCC pair 1
    box_pass<PLANE, true ><<<512, 256>>>(I1,        tA);
    box_pass<PLANE, true ><<<512, 256>>>(I1R,       tA + VOL);
    box_pass<128,   false><<<512, 256>>>(tA,        tB);
    box_pass<128,   false><<<512, 256>>>(tA + VOL,  tB + VOL);
    xpass_reduce<<<1024, 256>>>(tB, tB + VOL, I1, I1R, 4);

    finalize_kernel<<<1, 1>>>(out);
}

// round 3
// speedup vs baseline: 1.4561x; 1.4561x over previous
#include <cuda_runtime.h>
#include <math.h>

#define BVOL  (128*128*128)
#define VOL   (2*BVOL)          // 4,194,304
#define PLANE (128*128)
#define FVOL  (2*3*BVOL)        // 12,582,912

#define NLCC 400                // LCC blocks: 5x5 xy-tiles * 4 z-segs * 2 pairs * 2 batches
#define NLIN 488                // linear reduction blocks
#define NTOT (NLCC + NLIN)

__device__ double g_acc[12];
// 0 reg | 1 gg0 2 pp0 3 gp0 | 4 gg1 5 pp1 6 gp1 | 7 tvgp0 8 tvsum0 | 9 tvgp1 10 tvsum1

__global__ void zero_acc_kernel() {
    if (threadIdx.x < 12) g_acc[threadIdx.x] = 0.0;
}

__device__ __forceinline__ float warpSum(float v) {
#pragma unroll
    for (int o = 16; o; o >>= 1) v += __shfl_down_sync(0xffffffffu, v, o);
    return v;
}

__global__ void __launch_bounds__(1024, 2)
fused_main(const float* __restrict__ F0,  const float* __restrict__ F0g,
           const float* __restrict__ I0,  const float* __restrict__ I0R,
           const float* __restrict__ I1,  const float* __restrict__ I1R,
           const float* __restrict__ S0,  const float* __restrict__ S0g,
           const float* __restrict__ S1,  const float* __restrict__ S1g) {
    __shared__ float smZG[32][32];
    __shared__ float smZP[32][32];
    __shared__ float red[5][32];

    const int tx  = threadIdx.x;         // 0..31 (x within tile, warp = x-row)
    const int ty  = threadIdx.y;         // 0..31
    const int lin = ty * 32 + tx;
    const int lane = lin & 31, wid = lin >> 5;
    const int bid = blockIdx.x;

    if (bid < NLCC) {
        // ---------------- fully fused LCC ----------------
        int t = bid;
        int pb   = t & 3;  t >>= 2;      // pair*2 + batch
        int zseg = t & 3;  t >>= 2;
        int tyid = t % 5;
        int txid = t / 5;
        int pair = pb >> 1, n = pb & 1;
        const float* __restrict__ gt = pair ? I1  : I0;
        const float* __restrict__ pr = pair ? I1R : I0R;
        const int accBase = 1 + 3 * pair;

        const int x0 = txid * 28, y0 = tyid * 28, z0 = zseg * 32;
        const int gx = x0 + tx - 2, gy = y0 + ty - 2;
        const bool colValid = (gx >= 0) && (gx < 128) && (gy >= 0) && (gy < 128);
        const bool inter = (tx >= 2) && (tx < 30) && (ty >= 2) && (ty < 30) &&
                           (gx < 128) && (gy < 128);
        const long cbase = (long)n * BVOL + (long)gy * 128 + gx;

        // 5-register z windows (planes z-2..z+1 preloaded into g0..g3)
        float g0 = 0.f, g1 = 0.f, g2 = 0.f, g3 = 0.f;
        float p0 = 0.f, p1 = 0.f, p2 = 0.f, p3 = 0.f;
        {
            int zp = z0 - 2;
            if (colValid && zp >= 0) { g0 = gt[cbase + (long)zp * PLANE]; p0 = pr[cbase + (long)zp * PLANE]; }
            zp = z0 - 1;
            if (colValid && zp >= 0) { g1 = gt[cbase + (long)zp * PLANE]; p1 = pr[cbase + (long)zp * PLANE]; }
            if (colValid) {
                g2 = gt[cbase + (long)z0 * PLANE];       p2 = pr[cbase + (long)z0 * PLANE];
                g3 = gt[cbase + (long)(z0+1) * PLANE];   p3 = pr[cbase + (long)(z0+1) * PLANE];
            }
        }

        float agg = 0.f, app = 0.f, agp = 0.f;

#pragma unroll 4
        for (int zi = 0; zi < 32; zi++) {
            const int z  = z0 + zi;
            const int zl = z + 2;
            float ng = 0.f, np = 0.f;
            if (colValid && zl < 128) {
                ng = gt[cbase + (long)zl * PLANE];
                np = pr[cbase + (long)zl * PLANE];
            }
            // z-sum (5-tap) in registers, one smem write per tensor
            smZG[ty][tx] = ((g0 + g1) + (g2 + g3)) + ng;
            smZP[ty][tx] = ((p0 + p1) + (p2 + p3)) + np;
            __syncthreads();

            // y-sum: 5 smem reads (cross-thread in y)
            float ysG = 0.f, ysP = 0.f;
            if (ty >= 2 && ty < 30) {
                ysG = ((smZG[ty-2][tx] + smZG[ty-1][tx]) + (smZG[ty][tx] + smZG[ty+1][tx])) + smZG[ty+2][tx];
                ysP = ((smZP[ty-2][tx] + smZP[ty-1][tx]) + (smZP[ty][tx] + smZP[ty+1][tx])) + smZP[ty+2][tx];
            }
            // x-sum via warp shuffles (warp == one x-row)
            float gGm2 = __shfl_up_sync(0xffffffffu, ysG, 2);
            float gGm1 = __shfl_up_sync(0xffffffffu, ysG, 1);
            float gGp1 = __shfl_down_sync(0xffffffffu, ysG, 1);
            float gGp2 = __shfl_down_sync(0xffffffffu, ysG, 2);
            float gPm2 = __shfl_up_sync(0xffffffffu, ysP, 2);
            float gPm1 = __shfl_up_sync(0xffffffffu, ysP, 1);
            float gPp1 = __shfl_down_sync(0xffffffffu, ysP, 1);
            float gPp2 = __shfl_down_sync(0xffffffffu, ysP, 2);
            if (inter) {
                float mg = (((gGm2 + gGm1) + (ysG + gGp1)) + gGp2) * 0.008f;  // 1/125
                float mp = (((gPm2 + gPm1) + (ysP + gPp1)) + gPp2) * 0.008f;
                float dg = g2 - mg;   // g2 holds plane z (center)
                float dp = p2 - mp;
                agg = fmaf(dg, dg, agg);
                app = fmaf(dp, dp, app);
                agp = fmaf(dg, dp, agp);
            }
            __syncthreads();
            // slide windows
            g0 = g1; g1 = g2; g2 = g3; g3 = ng;
            p0 = p1; p1 = p2; p2 = p3; p3 = np;
        }

        // block reduction of 3 partials
        agg = warpSum(agg); app = warpSum(app); agp = warpSum(agp);
        if (lane == 0) { red[0][wid] = agg; red[1][wid] = app; red[2][wid] = agp; }
        __syncthreads();
        if (wid == 0) {
            float a = red[0][lane], b = red[1][lane], c = red[2][lane];
            a = warpSum(a); b = warpSum(b); c = warpSum(c);
            if (lane == 0) {
                atomicAdd(&g_acc[accBase + 0], (double)a);
                atomicAdd(&g_acc[accBase + 1], (double)b);
                atomicAdd(&g_acc[accBase + 2], (double)c);
            }
        }
    } else {
        // ---------------- linear reductions: reg + tversky x2 ----------------
        const int R = FVOL / 4;          // 3,145,728 float4s
        const int T = VOL / 4;           // 1,048,576
        const int tot = R + 2 * T;
        int i      = (bid - NLCC) * 1024 + lin;
        const int stride = NLIN * 1024;
        float sreg = 0.f, gp0 = 0.f, sm0 = 0.f, gp1 = 0.f, sm1 = 0.f;
        for (; i < tot; i += stride) {
            if (i < R) {
                float4 a = ((const float4*)F0)[i];
                float4 b = ((const float4*)F0g)[i];
                float d0 = a.x - b.x, d1 = a.y - b.y, d2 = a.z - b.z, d3 = a.w - b.w;
                sreg += (d0 * d0 + d1 * d1) + (d2 * d2 + d3 * d3);
            } else if (i < R + T) {
                int j = i - R;
                float4 a = ((const float4*)S0)[j];
                float4 b = ((const float4*)S0g)[j];
                gp0 += (a.x * b.x + a.y * b.y) + (a.z * b.z + a.w * b.w);
                sm0 += ((a.x + b.x) + (a.y + b.y)) + ((a.z + b.z) + (a.w + b.w));
            } else {
                int j = i - R - T;
                float4 a = ((const float4*)S1)[j];
                float4 b = ((const float4*)S1g)[j];
                gp1 += (a.x * b.x + a.y * b.y) + (a.z * b.z + a.w * b.w);
                sm1 += ((a.x + b.x) + (a.y + b.y)) + ((a.z + b.z) + (a.w + b.w));
            }
        }
        sreg = warpSum(sreg); gp0 = warpSum(gp0); sm0 = warpSum(sm0);
        gp1 = warpSum(gp1);  sm1 = warpSum(sm1);
        if (lane == 0) {
            red[0][wid] = sreg; red[1][wid] = gp0; red[2][wid] = sm0;
            red[3][wid] = gp1;  red[4][wid] = sm1;
        }
        __syncthreads();
        if (wid == 0) {
            float a = red[0][lane], b = red[1][lane], c = red[2][lane];
            float d = red[3][lane], e = red[4][lane];
            a = warpSum(a); b = warpSum(b); c = warpSum(c); d = warpSum(d); e = warpSum(e);
            if (lane == 0) {
                if (a != 0.f) atomicAdd(&g_acc[0],  (double)a);
                atomicAdd(&g_acc[7],  (double)b);
                atomicAdd(&g_acc[8],  (double)c);
                atomicAdd(&g_acc[9],  (double)d);
                atomicAdd(&g_acc[10], (double)e);
            }
        }
    }
}

__global__ void finalize_kernel(float* out) {
    double reg = sqrt(g_acc[0]) / (double)FVOL;

    double den0 = g_acc[1] * g_acc[2]; if (den0 < 1e-5) den0 = 1e-5;
    double lcc0 = -((g_acc[3] * g_acc[3]) / den0) / (double)VOL;
    double den1 = g_acc[4] * g_acc[5]; if (den1 < 1e-5) den1 = 1e-5;
    double lcc1 = -((g_acc[6] * g_acc[6]) / den1) / (double)VOL;

    double ds0 = g_acc[8];  if (ds0 < 1e-5) ds0 = 1e-5;
    double tv0 = -g_acc[7] / ds0;
    double ds1 = g_acc[10]; if (ds1 < 1e-5) ds1 = 1e-5;
    double tv1 = -g_acc[9] / ds1;

    out[0] = (float)(reg + 10.0 * (lcc0 + lcc1) + 10.0 * (tv0 + tv1));
}

extern "C" void kernel_launch(void* const* d_in, const int* in_sizes, int n_in,
                              void* d_out, int out_size) {
    const float* F0  = (const float*)d_in[0];
    const float* F0g = (const float*)d_in[1];
    const float* I0  = (const float*)d_in[2];
    const float* I0R = (const float*)d_in[3];
    const float* I1  = (const float*)d_in[4];
    const float* I1R = (const float*)d_in[5];
    const float* S0  = (const float*)d_in[6];
    const float* S0g = (const float*)d_in[7];
    const float* S1  = (const float*)d_in[8];
    const float* S1g = (const float*)d_in[9];
    float* out = (float*)d_out;

    zero_acc_kernel<<<1, 32>>>();
    dim3 blk(32, 32);
    fused_main<<<NTOT, blk>>>(F0, F0g, I0, I0R, I1, I1R, S0, S0g, S1, S1g);
    finalize_kernel<<<1, 1>>>(out);
}

// round 4
// speedup vs baseline: 1.4566x; 1.0004x over previous
#include <cuda_runtime.h>
#include <math.h>

#define BVOL  (128*128*128)
#define VOL   (2*BVOL)          // 4,194,304
#define PLANE (128*128)
#define FVOL  (2*3*BVOL)        // 12,582,912

#define NLCC 400                // 5x5 xy-tiles * 4 z-segs * 2 pairs * 2 batches
#define NLIN 488
#define NTOT (NLCC + NLIN)

__device__ double g_acc[12];    // zero-init; finalizer re-zeros each launch
__device__ unsigned int g_done; // zero-init; finalizer resets
// 0 reg | 1 gg0 2 pp0 3 gp0 | 4 gg1 5 pp1 6 gp1 | 7 tvgp0 8 tvsum0 | 9 tvgp1 10 tvsum1

__device__ __forceinline__ float warpSum(float v) {
#pragma unroll
    for (int o = 16; o; o >>= 1) v += __shfl_down_sync(0xffffffffu, v, o);
    return v;
}

__device__ __forceinline__ double accRead(int i) {
    return atomicAdd(&g_acc[i], 0.0);   // L2-coherent read
}

__global__ void __launch_bounds__(1024, 2)
fused_main(const float* __restrict__ F0,  const float* __restrict__ F0g,
           const float* __restrict__ I0,  const float* __restrict__ I0R,
           const float* __restrict__ I1,  const float* __restrict__ I1R,
           const float* __restrict__ S0,  const float* __restrict__ S0g,
           const float* __restrict__ S1,  const float* __restrict__ S1g,
           float* __restrict__ out) {
    __shared__ float smG[2][32][32];
    __shared__ float smP[2][32][32];
    __shared__ float red[5][32];

    const int tx  = threadIdx.x;          // warp = x-row
    const int ty  = threadIdx.y;
    const int lin = ty * 32 + tx;
    const int lane = lin & 31, wid = lin >> 5;
    const int bid = blockIdx.x;

    if (bid < NLCC) {
        // ---------------- fully fused LCC ----------------
        int t = bid;
        int pb   = t & 3;  t >>= 2;
        int zseg = t & 3;  t >>= 2;
        int tyid = t % 5;
        int txid = t / 5;
        int pair = pb >> 1, n = pb & 1;
        const float* __restrict__ gt = pair ? I1  : I0;
        const float* __restrict__ pr = pair ? I1R : I0R;
        const int accBase = 1 + 3 * pair;

        const int x0 = txid * 28, y0 = tyid * 28, z0 = zseg * 32;
        const int gx = x0 + tx - 2, gy = y0 + ty - 2;
        const bool colValid = (gx >= 0) && (gx < 128) && (gy >= 0) && (gy < 128);
        const bool inter = (tx >= 2) && (tx < 30) && (ty >= 2) && (ty < 30) &&
                           (gx < 128) && (gy < 128);
        const long cbase = (long)n * BVOL + (long)gy * 128 + gx;

        float g0 = 0.f, g1 = 0.f, g2 = 0.f, g3 = 0.f;
        float p0 = 0.f, p1 = 0.f, p2 = 0.f, p3 = 0.f;
        {
            int zp = z0 - 2;
            if (colValid && zp >= 0) { g0 = gt[cbase + (long)zp * PLANE]; p0 = pr[cbase + (long)zp * PLANE]; }
            zp = z0 - 1;
            if (colValid && zp >= 0) { g1 = gt[cbase + (long)zp * PLANE]; p1 = pr[cbase + (long)zp * PLANE]; }
            if (colValid) {
                g2 = gt[cbase + (long)z0 * PLANE];       p2 = pr[cbase + (long)z0 * PLANE];
                g3 = gt[cbase + (long)(z0+1) * PLANE];   p3 = pr[cbase + (long)(z0+1) * PLANE];
            }
        }

        float agg = 0.f, app = 0.f, agp = 0.f;

#pragma unroll 4
        for (int zi = 0; zi < 32; zi++) {
            const int buf = zi & 1;
            const int zl  = z0 + zi + 2;
            float ng = 0.f, np = 0.f;
            if (colValid && zl < 128) {
                ng = gt[cbase + (long)zl * PLANE];
                np = pr[cbase + (long)zl * PLANE];
            }
            smG[buf][ty][tx] = ((g0 + g1) + (g2 + g3)) + ng;
            smP[buf][ty][tx] = ((p0 + p1) + (p2 + p3)) + np;
            __syncthreads();

            float ysG = 0.f, ysP = 0.f;
            if (ty >= 2 && ty < 30) {
                ysG = ((smG[buf][ty-2][tx] + smG[buf][ty-1][tx]) + (smG[buf][ty][tx] + smG[buf][ty+1][tx])) + smG[buf][ty+2][tx];
                ysP = ((smP[buf][ty-2][tx] + smP[buf][ty-1][tx]) + (smP[buf][ty][tx] + smP[buf][ty+1][tx])) + smP[buf][ty+2][tx];
            }
            float gGm2 = __shfl_up_sync(0xffffffffu, ysG, 2);
            float gGm1 = __shfl_up_sync(0xffffffffu, ysG, 1);
            float gGp1 = __shfl_down_sync(0xffffffffu, ysG, 1);
            float gGp2 = __shfl_down_sync(0xffffffffu, ysG, 2);
            float gPm2 = __shfl_up_sync(0xffffffffu, ysP, 2);
            float gPm1 = __shfl_up_sync(0xffffffffu, ysP, 1);
            float gPp1 = __shfl_down_sync(0xffffffffu, ysP, 1);
            float gPp2 = __shfl_down_sync(0xffffffffu, ysP, 2);
            if (inter) {
                float mg = (((gGm2 + gGm1) + (ysG + gGp1)) + gGp2) * 0.008f;  // 1/125
                float mp = (((gPm2 + gPm1) + (ysP + gPp1)) + gPp2) * 0.008f;
                float dg = g2 - mg;
                float dp = p2 - mp;
                agg = fmaf(dg, dg, agg);
                app = fmaf(dp, dp, app);
                agp = fmaf(dg, dp, agp);
            }
            // no trailing sync: next iteration uses the other buffer; its
            // __syncthreads separates any same-buffer reuse two iters away.
            g0 = g1; g1 = g2; g2 = g3; g3 = ng;
            p0 = p1; p1 = p2; p2 = p3; p3 = np;
        }

        agg = warpSum(agg); app = warpSum(app); agp = warpSum(agp);
        if (lane == 0) { red[0][wid] = agg; red[1][wid] = app; red[2][wid] = agp; }
        __syncthreads();
        if (wid == 0) {
            float a = red[0][lane], b = red[1][lane], c = red[2][lane];
            a = warpSum(a); b = warpSum(b); c = warpSum(c);
            if (lane == 0) {
                atomicAdd(&g_acc[accBase + 0], (double)a);
                atomicAdd(&g_acc[accBase + 1], (double)b);
                atomicAdd(&g_acc[accBase + 2], (double)c);
            }
        }
    } else {
        // ---------------- linear reductions: reg + tversky x2 ----------------
        const int R = FVOL / 4;
        const int T = VOL / 4;
        const int tot = R + 2 * T;
        int i      = (bid - NLCC) * 1024 + lin;
        const int stride = NLIN * 1024;
        float sreg = 0.f, gp0 = 0.f, sm0 = 0.f, gp1 = 0.f, sm1 = 0.f;
        for (; i < tot; i += stride) {
            if (i < R) {
                float4 a = ((const float4*)F0)[i];
                float4 b = ((const float4*)F0g)[i];
                float d0 = a.x - b.x, d1 = a.y - b.y, d2 = a.z - b.z, d3 = a.w - b.w;
                sreg += (d0 * d0 + d1 * d1) + (d2 * d2 + d3 * d3);
            } else if (i < R + T) {
                int j = i - R;
                float4 a = ((const float4*)S0)[j];
                float4 b = ((const float4*)S0g)[j];
                gp0 += (a.x * b.x + a.y * b.y) + (a.z * b.z + a.w * b.w);
                sm0 += ((a.x + b.x) + (a.y + b.y)) + ((a.z + b.z) + (a.w + b.w));
            } else {
                int j = i - R - T;
                float4 a = ((const float4*)S1)[j];
                float4 b = ((const float4*)S1g)[j];
                gp1 += (a.x * b.x + a.y * b.y) + (a.z * b.z + a.w * b.w);
                sm1 += ((a.x + b.x) + (a.y + b.y)) + ((a.z + b.z) + (a.w + b.w));
            }
        }
        sreg = warpSum(sreg); gp0 = warpSum(gp0); sm0 = warpSum(sm0);
        gp1 = warpSum(gp1);  sm1 = warpSum(sm1);
        if (lane == 0) {
            red[0][wid] = sreg; red[1][wid] = gp0; red[2][wid] = sm0;
            red[3][wid] = gp1;  red[4][wid] = sm1;
        }
        __syncthreads();
        if (wid == 0) {
            float a = red[0][lane], b = red[1][lane], c = red[2][lane];
            float d = red[3][lane], e = red[4][lane];
            a = warpSum(a); b = warpSum(b); c = warpSum(c); d = warpSum(d); e = warpSum(e);
            if (lane == 0) {
                atomicAdd(&g_acc[0],  (double)a);
                atomicAdd(&g_acc[7],  (double)b);
                atomicAdd(&g_acc[8],  (double)c);
                atomicAdd(&g_acc[9],  (double)d);
                atomicAdd(&g_acc[10], (double)e);
            }
        }
    }

    // -------- last-block finalize (thread 0 of whichever block is last) -----
    if (lin == 0) {
        __threadfence();
        unsigned int old = atomicAdd(&g_done, 1u);
        if (old == NTOT - 1) {
            double a0 = accRead(0), a1 = accRead(1), a2 = accRead(2), a3 = accRead(3);
            double a4 = accRead(4), a5 = accRead(5), a6 = accRead(6), a7 = accRead(7);
            double a8 = accRead(8), a9 = accRead(9), a10 = accRead(10);

            double reg = sqrt(a0) / (double)FVOL;
            double den0 = a1 * a2; if (den0 < 1e-5) den0 = 1e-5;
            double lcc0 = -((a3 * a3) / den0) / (double)VOL;
            double den1 = a4 * a5; if (den1 < 1e-5) den1 = 1e-5;
            double lcc1 = -((a6 * a6) / den1) / (double)VOL;
            double ds0 = a8;  if (ds0 < 1e-5) ds0 = 1e-5;
            double tv0 = -a7 / ds0;
            double ds1 = a10; if (ds1 < 1e-5) ds1 = 1e-5;
            double tv1 = -a9 / ds1;

            out[0] = (float)(reg + 10.0 * (lcc0 + lcc1) + 10.0 * (tv0 + tv1));

            // reset for next launch / graph replay
#pragma unroll
            for (int k = 0; k < 12; k++) g_acc[k] = 0.0;
            __threadfence();
            g_done = 0u;
        }
    }
}

extern "C" void kernel_launch(void* const* d_in, const int* in_sizes, int n_in,
                              void* d_out, int out_size) {
    const float* F0  = (const float*)d_in[0];
    const float* F0g = (const float*)d_in[1];
    const float* I0  = (const float*)d_in[2];
    const float* I0R = (const float*)d_in[3];
    const float* I1  = (const float*)d_in[4];
    const float* I1R = (const float*)d_in[5];
    const float* S0  = (const float*)d_in[6];
    const float* S0g = (const float*)d_in[7];
    const float* S1  = (const float*)d_in[8];
    const float* S1g = (const float*)d_in[9];
    float* out = (float*)d_out;

    dim3 blk(32, 32);
    fused_main<<<NTOT, blk>>>(F0, F0g, I0, I0R, I1, I1R, S0, S0g, S1, S1g, out);
}